// round 14
// baseline (speedup 1.0000x reference)
// NerfMLP on GB300 (sm_103a HW, compute_103 PTX target -> legacy HMMA only).
// Round 13: m=4 blocks per warp (64 rows/warp) -- quarter the LDS per MMA.
//  - R12 finding: L1 crossbar still ~70% (weights LDS per MMA) caps tensor at 67%.
//  - Fix: each weight-fragment LDS.64 now serves 4 MMAs (was 2).
//  - 256 threads / 8 warps (2 per SMSP), TILE_M=512, ~235 regs (255 budget).
//  - ReLU in packed half2 domain (HMAX2) after cvt -- fewer epilogue instrs,
//    numerically identical (max(rn(x),0) == rn(max(x,0))).
//  - mma.sync.m16n8k16.f32.f16.f16.f32, bias in acc init, persistent CTAs.

#include <cuda_runtime.h>
#include <cuda_fp16.h>
#include <cstdint>

#define TILE_M 512

// SMEM layout (bytes)
#define OFF_W     0          // uint2 Wfrag[7*4*8*32] = 57344
#define OFF_BIAS  57344      // float [7*64]          = 1792
#define OFF_STEMW 59136      // float [96]            = 384
#define OFF_STEMB 59520      // float [32]            = 128
#define OFF_OUT   59648      // float [512*33]        = 67584
#define SMEM_BYTES 127232

__device__ __forceinline__ void mma_f16(float& c0, float& c1, float& c2, float& c3,
                                        uint32_t a0, uint32_t a1, uint32_t a2, uint32_t a3,
                                        uint32_t b0, uint32_t b1) {
    asm("mma.sync.aligned.m16n8k16.row.col.f32.f16.f16.f32 "
        "{%0,%1,%2,%3}, {%4,%5,%6,%7}, {%8,%9}, {%0,%1,%2,%3};"
        : "+f"(c0), "+f"(c1), "+f"(c2), "+f"(c3)
        : "r"(a0), "r"(a1), "r"(a2), "r"(a3), "r"(b0), "r"(b1));
}

__device__ __forceinline__ uint32_t pack_h2(float v0, float v1) {
    __half2 p = __floats2half2_rn(v0, v1);
    return *reinterpret_cast<uint32_t*>(&p);
}

// pack + ReLU in fp16 domain: max(rn(x),0) == rn(max(x,0))
__device__ __forceinline__ uint32_t pack_relu_h2(float v0, float v1) {
    __half2 p = __floats2half2_rn(v0, v1);
    __half2 z = __floats2half2_rn(0.f, 0.f);
    __half2 r = __hmax2(p, z);
    return *reinterpret_cast<uint32_t*>(&r);
}

__global__ void __launch_bounds__(256, 1)
nerf_mlp_kernel(const float* __restrict__ x,
                const float* __restrict__ noise,
                const float* __restrict__ stem_w,
                const float* __restrict__ stem_b,
                const float* __restrict__ Ws,
                const float* __restrict__ bs,
                const float* __restrict__ sigma_w,
                const float* __restrict__ sigma_b,
                const float* __restrict__ rgb_w,
                const float* __restrict__ rgb_b,
                float* __restrict__ out,
                int N, int nTiles) {
    extern __shared__ char sm[];
    uint2*  Wfr   = (uint2*)(sm + OFF_W);
    float*  biasS = (float*)(sm + OFF_BIAS);
    float*  stemW = (float*)(sm + OFF_STEMW);
    float*  stemB = (float*)(sm + OFF_STEMB);
    float*  smOut = (float*)(sm + OFF_OUT);

    const int tid  = threadIdx.x;
    const int lane = tid & 31;
    const int wid  = tid >> 5;          // 0..7
    const int c    = lane & 3;          // quad column selector
    const int rq   = lane >> 2;         // row-in-8 / B-frag n index

    // ---- one-time weight staging: fp16 fragments in per-lane layout ----
    // frag (l, kc, nb, lane): b0 packs W(kc*16 + 2*(lane&3) + {0,1}, n),
    // b1 packs +8 in k, with n = nb*8 + lane>>2.
    for (int fi = tid; fi < 7 * 4 * 8 * 32; fi += 256) {
        int fl = fi & 31;
        int nb = (fi >> 5) & 7;
        int kc = (fi >> 8) & 3;
        int l  = fi >> 10;
        int k0 = (fl & 3) * 2;
        int n  = nb * 8 + (fl >> 2);
        float w[4];
        #pragma unroll
        for (int q = 0; q < 4; q++) {
            int k = kc * 16 + k0 + (q >> 1) * 8 + (q & 1);
            float v;
            if (l < 6)        v = Ws[(l << 12) + (k << 6) + n];
            else if (n < 32)  v = rgb_w[(k << 5) + n];
            else if (n == 32) v = sigma_w[k];
            else              v = 0.0f;
            w[q] = v;
        }
        Wfr[fi] = make_uint2(pack_h2(w[0], w[1]), pack_h2(w[2], w[3]));
    }
    for (int i = tid; i < 7 * 64; i += 256) {
        int l = i >> 6, j = i & 63;
        float v;
        if (l < 6)        v = bs[i];
        else if (j < 32)  v = rgb_b[j];
        else if (j == 32) v = sigma_b[0];
        else              v = 0.0f;
        biasS[i] = v;
    }
    if (tid < 96) stemW[tid] = stem_w[tid];
    if (tid < 32) stemB[tid] = stem_b[tid];
    __syncthreads();

    // warp owns 64 rows: thread rows = lrow0 + m*16 + {0,8}, m = 0..3
    const int lrow0 = wid * 64 + rq;

    for (int t = blockIdx.x; t < nTiles; t += gridDim.x) {
        const long rowBase = (long)t * TILE_M + lrow0;

        uint32_t A[4][4][4];   // [m-block][kc][a0..a3], fp16x2

        // ---- first-layer input: concat(stem(x), noise) -> fp16 A frags ----
        #pragma unroll
        for (int m = 0; m < 4; m++) {
            long rl = rowBase + m * 16;
            long rh = rl + 8;
            bool vl = rl < N, vh = rh < N;
            float xl0 = 0, xl1 = 0, xl2 = 0, xh0 = 0, xh1 = 0, xh2 = 0;
            if (vl) { xl0 = x[rl * 3]; xl1 = x[rl * 3 + 1]; xl2 = x[rl * 3 + 2]; }
            if (vh) { xh0 = x[rh * 3]; xh1 = x[rh * 3 + 1]; xh2 = x[rh * 3 + 2]; }
            #pragma unroll
            for (int kc = 0; kc < 2; kc++) {          // stem cols 0..31
                #pragma unroll
                for (int h8 = 0; h8 < 2; h8++) {
                    int j = kc * 16 + 2 * c + h8 * 8;
                    float2 w0 = *(const float2*)(stemW + j);
                    float2 w1 = *(const float2*)(stemW + 32 + j);
                    float2 w2 = *(const float2*)(stemW + 64 + j);
                    float2 bb = *(const float2*)(stemB + j);
                    float sl0 = bb.x + xl0 * w0.x + xl1 * w1.x + xl2 * w2.x;
                    float sl1 = bb.y + xl0 * w0.y + xl1 * w1.y + xl2 * w2.y;
                    float sh0 = bb.x + xh0 * w0.x + xh1 * w1.x + xh2 * w2.x;
                    float sh1 = bb.y + xh0 * w0.y + xh1 * w1.y + xh2 * w2.y;
                    A[m][kc][h8 * 2]     = pack_h2(sl0, sl1);
                    A[m][kc][h8 * 2 + 1] = pack_h2(sh0, sh1);
                }
            }
            #pragma unroll
            for (int kc = 2; kc < 4; kc++) {          // noise cols 32..63
                #pragma unroll
                for (int h8 = 0; h8 < 2; h8++) {
                    int nc = (kc - 2) * 16 + 2 * c + h8 * 8;
                    float2 nl = vl ? *(const float2*)(noise + rl * 32 + nc) : make_float2(0, 0);
                    float2 nh = vh ? *(const float2*)(noise + rh * 32 + nc) : make_float2(0, 0);
                    A[m][kc][h8 * 2]     = pack_h2(nl.x, nl.y);
                    A[m][kc][h8 * 2 + 1] = pack_h2(nh.x, nh.y);
                }
            }
        }

        // ---- 7 layers: one weight LDS serves all 4 m-blocks ----
        float acc[4][8][4];
        for (int l = 0; l < 7; l++) {
            #pragma unroll
            for (int nb = 0; nb < 8; nb++) {
                float2 bb = *(const float2*)(biasS + l * 64 + nb * 8 + 2 * c);
                #pragma unroll
                for (int m = 0; m < 4; m++) {
                    acc[m][nb][0] = bb.x; acc[m][nb][1] = bb.y;
                    acc[m][nb][2] = bb.x; acc[m][nb][3] = bb.y;
                }
            }
            #pragma unroll
            for (int kc = 0; kc < 4; kc++) {
                const uint2* pw = Wfr + ((l * 4 + kc) * 8) * 32 + lane;
                uint2 bfr[8];
                #pragma unroll
                for (int nb = 0; nb < 8; nb++) bfr[nb] = pw[nb * 32];
                #pragma unroll
                for (int nb = 0; nb < 8; nb++) {
                    #pragma unroll
                    for (int m = 0; m < 4; m++)
                        mma_f16(acc[m][nb][0], acc[m][nb][1], acc[m][nb][2], acc[m][nb][3],
                                A[m][kc][0], A[m][kc][1], A[m][kc][2], A[m][kc][3],
                                bfr[nb].x, bfr[nb].y);
                }
            }
            if (l < 6) {
                // C-frag (nb pair 2kc, 2kc+1) -> next-layer A-frag kc, ReLU in h2
                #pragma unroll
                for (int m = 0; m < 4; m++)
                    #pragma unroll
                    for (int kc = 0; kc < 4; kc++) {
                        A[m][kc][0] = pack_relu_h2(acc[m][2 * kc][0], acc[m][2 * kc][1]);
                        A[m][kc][1] = pack_relu_h2(acc[m][2 * kc][2], acc[m][2 * kc][3]);
                        A[m][kc][2] = pack_relu_h2(acc[m][2 * kc + 1][0], acc[m][2 * kc + 1][1]);
                        A[m][kc][3] = pack_relu_h2(acc[m][2 * kc + 1][2], acc[m][2 * kc + 1][3]);
                    }
            }
        }

        // ---- head epilogue: stage rgb (cols 0..31) + sigma (col 32) per-warp ----
        #pragma unroll
        for (int m = 0; m < 4; m++) {
            int sl = lrow0 + m * 16;     // tile-local rows
            int sh = sl + 8;
            #pragma unroll
            for (int nb = 0; nb < 4; nb++) {
                int j = nb * 8 + 2 * c;
                smOut[sl * 33 + j]     = acc[m][nb][0];
                smOut[sl * 33 + j + 1] = acc[m][nb][1];
                smOut[sh * 33 + j]     = acc[m][nb][2];
                smOut[sh * 33 + j + 1] = acc[m][nb][3];
            }
            if (c == 0) {
                smOut[sl * 33 + 32] = acc[m][4][0];
                smOut[sh * 33 + 32] = acc[m][4][2];
            }
        }
        __syncwarp();
        {
            long gBase = (long)t * (TILE_M * 33) + (long)wid * (64 * 33);
            int  sBase = wid * (64 * 33);
            long rowsLeft = N - (long)t * TILE_M - wid * 64;
            int nfl = 64 * 33;
            if (rowsLeft < 64) nfl = rowsLeft > 0 ? (int)rowsLeft * 33 : 0;
            for (int i = lane; i < nfl; i += 32)
                out[gBase + i] = smOut[sBase + i];
        }
        __syncwarp();
    }
}

extern "C" void kernel_launch(void* const* d_in, const int* in_sizes, int n_in,
                              void* d_out, int out_size) {
    const float* x       = (const float*)d_in[0];
    const float* noise   = (const float*)d_in[1];
    const float* stem_w  = (const float*)d_in[2];
    const float* stem_b  = (const float*)d_in[3];
    const float* Ws      = (const float*)d_in[4];
    const float* bs      = (const float*)d_in[5];
    const float* sigma_w = (const float*)d_in[6];
    const float* sigma_b = (const float*)d_in[7];
    const float* rgb_w   = (const float*)d_in[8];
    const float* rgb_b   = (const float*)d_in[9];
    float* out = (float*)d_out;

    int N = in_sizes[0] / 3;
    int nTiles = (N + TILE_M - 1) / TILE_M;   // 2,097,152 / 512 = 4096

    cudaFuncSetAttribute(nerf_mlp_kernel,
                         cudaFuncAttributeMaxDynamicSharedMemorySize, SMEM_BYTES);

    int dev = 0, sms = 148;
    cudaGetDevice(&dev);
    cudaDeviceGetAttribute(&sms, cudaDevAttrMultiProcessorCount, dev);
    int grid = nTiles < sms ? nTiles : sms;

    nerf_mlp_kernel<<<grid, 256, SMEM_BYTES>>>(
        x, noise, stem_w, stem_b, Ws, bs, sigma_w, sigma_b, rgb_w, rgb_b,
        out, N, nTiles);
}

// round 15
// speedup vs baseline: 1.1006x; 1.1006x over previous
// NerfMLP on GB300 (sm_103a HW, compute_103 PTX target -> legacy HMMA only).
// Round 14: revert to R12 shape (m=2, 384 thr, 12 warps) + instruction diet.
//  - R13 lesson: 2 warps/SMSP starves latency hiding; 3/SMSP is the sweet spot.
//  - LDS.128 weight frags: two nb-fragments per load -> 16 LDS.128/warp-layer
//    (was 32 LDS.64). Same bytes, half the issue slots.
//  - ReLU in packed half2 (HMAX2) -- verified bit-identical in R13.
//  - float4 fast-path for the output copy on full tiles.
//  - mma.sync.m16n8k16.f32.f16.f16.f32, bias in acc init, persistent CTAs.

#include <cuda_runtime.h>
#include <cuda_fp16.h>
#include <cstdint>

#define TILE_M 384

// SMEM layout (bytes)
#define OFF_W     0          // uint4 Wfr4[7*4*4*32] = 57344
#define OFF_BIAS  57344      // float [7*64]          = 1792
#define OFF_STEMW 59136      // float [96]            = 384
#define OFF_STEMB 59520      // float [32]            = 128
#define OFF_OUT   59648      // float [384*33]        = 50688
#define SMEM_BYTES 110336

__device__ __forceinline__ void mma_f16(float& c0, float& c1, float& c2, float& c3,
                                        uint32_t a0, uint32_t a1, uint32_t a2, uint32_t a3,
                                        uint32_t b0, uint32_t b1) {
    asm("mma.sync.aligned.m16n8k16.row.col.f32.f16.f16.f32 "
        "{%0,%1,%2,%3}, {%4,%5,%6,%7}, {%8,%9}, {%0,%1,%2,%3};"
        : "+f"(c0), "+f"(c1), "+f"(c2), "+f"(c3)
        : "r"(a0), "r"(a1), "r"(a2), "r"(a3), "r"(b0), "r"(b1));
}

__device__ __forceinline__ uint32_t pack_h2(float v0, float v1) {
    __half2 p = __floats2half2_rn(v0, v1);
    return *reinterpret_cast<uint32_t*>(&p);
}

// pack + ReLU in fp16 domain: max(rn(x),0) == rn(max(x,0))  (verified R13)
__device__ __forceinline__ uint32_t pack_relu_h2(float v0, float v1) {
    __half2 p = __floats2half2_rn(v0, v1);
    __half2 z = __floats2half2_rn(0.f, 0.f);
    __half2 r = __hmax2(p, z);
    return *reinterpret_cast<uint32_t*>(&r);
}

__global__ void __launch_bounds__(384, 1)
nerf_mlp_kernel(const float* __restrict__ x,
                const float* __restrict__ noise,
                const float* __restrict__ stem_w,
                const float* __restrict__ stem_b,
                const float* __restrict__ Ws,
                const float* __restrict__ bs,
                const float* __restrict__ sigma_w,
                const float* __restrict__ sigma_b,
                const float* __restrict__ rgb_w,
                const float* __restrict__ rgb_b,
                float* __restrict__ out,
                int N, int nTiles) {
    extern __shared__ char sm[];
    uint4*  Wfr4  = (uint4*)(sm + OFF_W);
    float*  biasS = (float*)(sm + OFF_BIAS);
    float*  stemW = (float*)(sm + OFF_STEMW);
    float*  stemB = (float*)(sm + OFF_STEMB);
    float*  smOut = (float*)(sm + OFF_OUT);

    const int tid  = threadIdx.x;
    const int lane = tid & 31;
    const int wid  = tid >> 5;          // 0..11
    const int c    = lane & 3;          // quad column selector
    const int rq   = lane >> 2;         // row-in-8 / B-frag n index

    // ---- one-time weight staging: fp16 fragments, uint4 = two nb-blocks ----
    // Wfr4[((l*4+kc)*4+p)*32 + lane] = {b0(nb=2p), b1(nb=2p), b0(nb=2p+1), b1(nb=2p+1)}
    // where b0 packs W(kc*16 + 2*(lane&3) + {0,1}, n), b1 packs +8 in k,
    // n = nb*8 + (lane>>2).
    for (int fi = tid; fi < 7 * 4 * 4 * 32; fi += 384) {
        int fl = fi & 31;
        int p  = (fi >> 5) & 3;
        int kc = (fi >> 7) & 3;
        int l  = fi >> 9;
        int k0 = (fl & 3) * 2;
        uint32_t v[4];
        #pragma unroll
        for (int s = 0; s < 2; s++) {
            int n = (2 * p + s) * 8 + (fl >> 2);
            float w[4];
            #pragma unroll
            for (int q = 0; q < 4; q++) {
                int k = kc * 16 + k0 + (q >> 1) * 8 + (q & 1);
                float vv;
                if (l < 6)        vv = Ws[(l << 12) + (k << 6) + n];
                else if (n < 32)  vv = rgb_w[(k << 5) + n];
                else if (n == 32) vv = sigma_w[k];
                else              vv = 0.0f;
                w[q] = vv;
            }
            v[2 * s]     = pack_h2(w[0], w[1]);
            v[2 * s + 1] = pack_h2(w[2], w[3]);
        }
        Wfr4[fi] = make_uint4(v[0], v[1], v[2], v[3]);
    }
    for (int i = tid; i < 7 * 64; i += 384) {
        int l = i >> 6, j = i & 63;
        float v;
        if (l < 6)        v = bs[i];
        else if (j < 32)  v = rgb_b[j];
        else if (j == 32) v = sigma_b[0];
        else              v = 0.0f;
        biasS[i] = v;
    }
    if (tid < 96) stemW[tid] = stem_w[tid];
    if (tid < 32) stemB[tid] = stem_b[tid];
    __syncthreads();

    // warp owns 32 rows: thread rows = lrow0 + {0,8,16,24} (m-block*16 + {0,8})
    const int lrow0 = wid * 32 + rq;

    for (int t = blockIdx.x; t < nTiles; t += gridDim.x) {
        const long rowBase = (long)t * TILE_M + lrow0;

        uint32_t A[2][4][4];   // [m-block][kc][a0..a3], fp16x2

        // ---- first-layer input: concat(stem(x), noise) -> fp16 A frags ----
        #pragma unroll
        for (int m = 0; m < 2; m++) {
            long rl = rowBase + m * 16;
            long rh = rl + 8;
            bool vl = rl < N, vh = rh < N;
            float xl0 = 0, xl1 = 0, xl2 = 0, xh0 = 0, xh1 = 0, xh2 = 0;
            if (vl) { xl0 = x[rl * 3]; xl1 = x[rl * 3 + 1]; xl2 = x[rl * 3 + 2]; }
            if (vh) { xh0 = x[rh * 3]; xh1 = x[rh * 3 + 1]; xh2 = x[rh * 3 + 2]; }
            #pragma unroll
            for (int kc = 0; kc < 2; kc++) {          // stem cols 0..31
                #pragma unroll
                for (int h8 = 0; h8 < 2; h8++) {
                    int j = kc * 16 + 2 * c + h8 * 8;
                    float2 w0 = *(const float2*)(stemW + j);
                    float2 w1 = *(const float2*)(stemW + 32 + j);
                    float2 w2 = *(const float2*)(stemW + 64 + j);
                    float2 bb = *(const float2*)(stemB + j);
                    float sl0 = bb.x + xl0 * w0.x + xl1 * w1.x + xl2 * w2.x;
                    float sl1 = bb.y + xl0 * w0.y + xl1 * w1.y + xl2 * w2.y;
                    float sh0 = bb.x + xh0 * w0.x + xh1 * w1.x + xh2 * w2.x;
                    float sh1 = bb.y + xh0 * w0.y + xh1 * w1.y + xh2 * w2.y;
                    A[m][kc][h8 * 2]     = pack_h2(sl0, sl1);
                    A[m][kc][h8 * 2 + 1] = pack_h2(sh0, sh1);
                }
            }
            #pragma unroll
            for (int kc = 2; kc < 4; kc++) {          // noise cols 32..63
                #pragma unroll
                for (int h8 = 0; h8 < 2; h8++) {
                    int nc = (kc - 2) * 16 + 2 * c + h8 * 8;
                    float2 nl = vl ? *(const float2*)(noise + rl * 32 + nc) : make_float2(0, 0);
                    float2 nh = vh ? *(const float2*)(noise + rh * 32 + nc) : make_float2(0, 0);
                    A[m][kc][h8 * 2]     = pack_h2(nl.x, nl.y);
                    A[m][kc][h8 * 2 + 1] = pack_h2(nh.x, nh.y);
                }
            }
        }

        // ---- 7 layers: LDS.128 weight frags, each serves 2 nb x 2 m MMAs ----
        float acc[2][8][4];
        for (int l = 0; l < 7; l++) {
            #pragma unroll
            for (int nb = 0; nb < 8; nb++) {
                float2 bb = *(const float2*)(biasS + l * 64 + nb * 8 + 2 * c);
                #pragma unroll
                for (int m = 0; m < 2; m++) {
                    acc[m][nb][0] = bb.x; acc[m][nb][1] = bb.y;
                    acc[m][nb][2] = bb.x; acc[m][nb][3] = bb.y;
                }
            }
            #pragma unroll
            for (int kc = 0; kc < 4; kc++) {
                const uint4* pw = Wfr4 + ((l * 4 + kc) * 4) * 32 + lane;
                uint4 q[4];
                #pragma unroll
                for (int p = 0; p < 4; p++) q[p] = pw[p * 32];
                #pragma unroll
                for (int p = 0; p < 4; p++) {
                    int nb0 = 2 * p, nb1 = 2 * p + 1;
                    mma_f16(acc[0][nb0][0], acc[0][nb0][1], acc[0][nb0][2], acc[0][nb0][3],
                            A[0][kc][0], A[0][kc][1], A[0][kc][2], A[0][kc][3],
                            q[p].x, q[p].y);
                    mma_f16(acc[1][nb0][0], acc[1][nb0][1], acc[1][nb0][2], acc[1][nb0][3],
                            A[1][kc][0], A[1][kc][1], A[1][kc][2], A[1][kc][3],
                            q[p].x, q[p].y);
                    mma_f16(acc[0][nb1][0], acc[0][nb1][1], acc[0][nb1][2], acc[0][nb1][3],
                            A[0][kc][0], A[0][kc][1], A[0][kc][2], A[0][kc][3],
                            q[p].z, q[p].w);
                    mma_f16(acc[1][nb1][0], acc[1][nb1][1], acc[1][nb1][2], acc[1][nb1][3],
                            A[1][kc][0], A[1][kc][1], A[1][kc][2], A[1][kc][3],
                            q[p].z, q[p].w);
                }
            }
            if (l < 6) {
                // C-frag (nb pair 2kc, 2kc+1) -> next-layer A-frag kc, ReLU in h2
                #pragma unroll
                for (int m = 0; m < 2; m++)
                    #pragma unroll
                    for (int kc = 0; kc < 4; kc++) {
                        A[m][kc][0] = pack_relu_h2(acc[m][2 * kc][0], acc[m][2 * kc][1]);
                        A[m][kc][1] = pack_relu_h2(acc[m][2 * kc][2], acc[m][2 * kc][3]);
                        A[m][kc][2] = pack_relu_h2(acc[m][2 * kc + 1][0], acc[m][2 * kc + 1][1]);
                        A[m][kc][3] = pack_relu_h2(acc[m][2 * kc + 1][2], acc[m][2 * kc + 1][3]);
                    }
            }
        }

        // ---- head epilogue: stage rgb (cols 0..31) + sigma (col 32) per-warp ----
        #pragma unroll
        for (int m = 0; m < 2; m++) {
            int sl = lrow0 + m * 16;     // tile-local rows
            int sh = sl + 8;
            #pragma unroll
            for (int nb = 0; nb < 4; nb++) {
                int j = nb * 8 + 2 * c;
                smOut[sl * 33 + j]     = acc[m][nb][0];
                smOut[sl * 33 + j + 1] = acc[m][nb][1];
                smOut[sh * 33 + j]     = acc[m][nb][2];
                smOut[sh * 33 + j + 1] = acc[m][nb][3];
            }
            if (c == 0) {
                smOut[sl * 33 + 32] = acc[m][4][0];
                smOut[sh * 33 + 32] = acc[m][4][2];
            }
        }
        __syncwarp();
        {
            long gBase = (long)t * (TILE_M * 33) + (long)wid * (32 * 33);
            int  sBase = wid * (32 * 33);
            long rowsLeft = N - (long)t * TILE_M - wid * 32;
            if (rowsLeft >= 32) {
                // full warp-chunk: 1056 floats = 264 float4 (all bases 16B-aligned)
                const float4* s4 = (const float4*)(smOut + sBase);
                float4*       g4 = (float4*)(out + gBase);
                #pragma unroll
                for (int it = 0; it < 8; it++)
                    g4[lane + it * 32] = s4[lane + it * 32];
                if (lane < 8) g4[lane + 256] = s4[lane + 256];
            } else if (rowsLeft > 0) {
                int nfl = (int)rowsLeft * 33;
                for (int i = lane; i < nfl; i += 32)
                    out[gBase + i] = smOut[sBase + i];
            }
        }
        __syncwarp();
    }
}

extern "C" void kernel_launch(void* const* d_in, const int* in_sizes, int n_in,
                              void* d_out, int out_size) {
    const float* x       = (const float*)d_in[0];
    const float* noise   = (const float*)d_in[1];
    const float* stem_w  = (const float*)d_in[2];
    const float* stem_b  = (const float*)d_in[3];
    const float* Ws      = (const float*)d_in[4];
    const float* bs      = (const float*)d_in[5];
    const float* sigma_w = (const float*)d_in[6];
    const float* sigma_b = (const float*)d_in[7];
    const float* rgb_w   = (const float*)d_in[8];
    const float* rgb_b   = (const float*)d_in[9];
    float* out = (float*)d_out;

    int N = in_sizes[0] / 3;
    int nTiles = (N + TILE_M - 1) / TILE_M;   // ceil(2,097,152 / 384) = 5462

    cudaFuncSetAttribute(nerf_mlp_kernel,
                         cudaFuncAttributeMaxDynamicSharedMemorySize, SMEM_BYTES);

    int dev = 0, sms = 148;
    cudaGetDevice(&dev);
    cudaDeviceGetAttribute(&sms, cudaDevAttrMultiProcessorCount, dev);
    int grid = nTiles < sms ? nTiles : sms;

    nerf_mlp_kernel<<<grid, 384, SMEM_BYTES>>>(
        x, noise, stem_w, stem_b, Ws, bs, sigma_w, sigma_b, rgb_w, rgb_b,
        out, N, nTiles);
}

// round 16
// speedup vs baseline: 1.1694x; 1.0625x over previous
// NerfMLP on GB300 (sm_103a HW, compute_103 PTX target -> legacy HMMA only).
// Round 15: R14 shape (m=2, 384 thr, 12 warps) + unrolled layers + L2 prefetch.
//  - Layer loop fully unrolled: weight/bias addresses become immediates,
//    kills the per-layer IMAD chains (alu was 20%).
//  - prefetch.global.L2 for next tile's noise/x right after input build:
//    next tile-start loads hit L2 (~234 cyc) instead of DRAM (~600).
//  - LDS.128 weight frags (2 nb per load), ReLU in packed half2 (bit-identical),
//    float4 output fast path, bias in acc init, persistent CTAs.

#include <cuda_runtime.h>
#include <cuda_fp16.h>
#include <cstdint>

#define TILE_M 384

// SMEM layout (bytes)
#define OFF_W     0          // uint4 Wfr4[7*4*4*32] = 57344
#define OFF_BIAS  57344      // float [7*64]          = 1792
#define OFF_STEMW 59136      // float [96]            = 384
#define OFF_STEMB 59520      // float [32]            = 128
#define OFF_OUT   59648      // float [384*33]        = 50688
#define SMEM_BYTES 110336

__device__ __forceinline__ void mma_f16(float& c0, float& c1, float& c2, float& c3,
                                        uint32_t a0, uint32_t a1, uint32_t a2, uint32_t a3,
                                        uint32_t b0, uint32_t b1) {
    asm("mma.sync.aligned.m16n8k16.row.col.f32.f16.f16.f32 "
        "{%0,%1,%2,%3}, {%4,%5,%6,%7}, {%8,%9}, {%0,%1,%2,%3};"
        : "+f"(c0), "+f"(c1), "+f"(c2), "+f"(c3)
        : "r"(a0), "r"(a1), "r"(a2), "r"(a3), "r"(b0), "r"(b1));
}

__device__ __forceinline__ uint32_t pack_h2(float v0, float v1) {
    __half2 p = __floats2half2_rn(v0, v1);
    return *reinterpret_cast<uint32_t*>(&p);
}

// pack + ReLU in fp16 domain: max(rn(x),0) == rn(max(x,0))  (verified R13/R14)
__device__ __forceinline__ uint32_t pack_relu_h2(float v0, float v1) {
    __half2 p = __floats2half2_rn(v0, v1);
    __half2 z = __floats2half2_rn(0.f, 0.f);
    __half2 r = __hmax2(p, z);
    return *reinterpret_cast<uint32_t*>(&r);
}

__device__ __forceinline__ void prefetch_l2(const void* p) {
    asm volatile("prefetch.global.L2 [%0];" :: "l"(p));
}

__global__ void __launch_bounds__(384, 1)
nerf_mlp_kernel(const float* __restrict__ x,
                const float* __restrict__ noise,
                const float* __restrict__ stem_w,
                const float* __restrict__ stem_b,
                const float* __restrict__ Ws,
                const float* __restrict__ bs,
                const float* __restrict__ sigma_w,
                const float* __restrict__ sigma_b,
                const float* __restrict__ rgb_w,
                const float* __restrict__ rgb_b,
                float* __restrict__ out,
                int N, int nTiles) {
    extern __shared__ char sm[];
    uint4*  Wfr4  = (uint4*)(sm + OFF_W);
    float*  biasS = (float*)(sm + OFF_BIAS);
    float*  stemW = (float*)(sm + OFF_STEMW);
    float*  stemB = (float*)(sm + OFF_STEMB);
    float*  smOut = (float*)(sm + OFF_OUT);

    const int tid  = threadIdx.x;
    const int lane = tid & 31;
    const int wid  = tid >> 5;          // 0..11
    const int c    = lane & 3;          // quad column selector
    const int rq   = lane >> 2;         // row-in-8 / B-frag n index

    // ---- one-time weight staging: fp16 fragments, uint4 = two nb-blocks ----
    // Wfr4[((l*4+kc)*4+p)*32 + lane] = {b0(nb=2p), b1(nb=2p), b0(nb=2p+1), b1(nb=2p+1)}
    // where b0 packs W(kc*16 + 2*(lane&3) + {0,1}, n), b1 packs +8 in k,
    // n = nb*8 + (lane>>2).
    for (int fi = tid; fi < 7 * 4 * 4 * 32; fi += 384) {
        int fl = fi & 31;
        int p  = (fi >> 5) & 3;
        int kc = (fi >> 7) & 3;
        int l  = fi >> 9;
        int k0 = (fl & 3) * 2;
        uint32_t v[4];
        #pragma unroll
        for (int s = 0; s < 2; s++) {
            int n = (2 * p + s) * 8 + (fl >> 2);
            float w[4];
            #pragma unroll
            for (int q = 0; q < 4; q++) {
                int k = kc * 16 + k0 + (q >> 1) * 8 + (q & 1);
                float vv;
                if (l < 6)        vv = Ws[(l << 12) + (k << 6) + n];
                else if (n < 32)  vv = rgb_w[(k << 5) + n];
                else if (n == 32) vv = sigma_w[k];
                else              vv = 0.0f;
                w[q] = vv;
            }
            v[2 * s]     = pack_h2(w[0], w[1]);
            v[2 * s + 1] = pack_h2(w[2], w[3]);
        }
        Wfr4[fi] = make_uint4(v[0], v[1], v[2], v[3]);
    }
    for (int i = tid; i < 7 * 64; i += 384) {
        int l = i >> 6, j = i & 63;
        float v;
        if (l < 6)        v = bs[i];
        else if (j < 32)  v = rgb_b[j];
        else if (j == 32) v = sigma_b[0];
        else              v = 0.0f;
        biasS[i] = v;
    }
    if (tid < 96) stemW[tid] = stem_w[tid];
    if (tid < 32) stemB[tid] = stem_b[tid];
    __syncthreads();

    // warp owns 32 rows: thread rows = lrow0 + {0,8,16,24} (m-block*16 + {0,8})
    const int lrow0 = wid * 32 + rq;

    for (int t = blockIdx.x; t < nTiles; t += gridDim.x) {
        const long rowBase = (long)t * TILE_M + lrow0;

        uint32_t A[2][4][4];   // [m-block][kc][a0..a3], fp16x2

        // ---- first-layer input: concat(stem(x), noise) -> fp16 A frags ----
        #pragma unroll
        for (int m = 0; m < 2; m++) {
            long rl = rowBase + m * 16;
            long rh = rl + 8;
            bool vl = rl < N, vh = rh < N;
            float xl0 = 0, xl1 = 0, xl2 = 0, xh0 = 0, xh1 = 0, xh2 = 0;
            if (vl) { xl0 = x[rl * 3]; xl1 = x[rl * 3 + 1]; xl2 = x[rl * 3 + 2]; }
            if (vh) { xh0 = x[rh * 3]; xh1 = x[rh * 3 + 1]; xh2 = x[rh * 3 + 2]; }
            #pragma unroll
            for (int kc = 0; kc < 2; kc++) {          // stem cols 0..31
                #pragma unroll
                for (int h8 = 0; h8 < 2; h8++) {
                    int j = kc * 16 + 2 * c + h8 * 8;
                    float2 w0 = *(const float2*)(stemW + j);
                    float2 w1 = *(const float2*)(stemW + 32 + j);
                    float2 w2 = *(const float2*)(stemW + 64 + j);
                    float2 bb = *(const float2*)(stemB + j);
                    float sl0 = bb.x + xl0 * w0.x + xl1 * w1.x + xl2 * w2.x;
                    float sl1 = bb.y + xl0 * w0.y + xl1 * w1.y + xl2 * w2.y;
                    float sh0 = bb.x + xh0 * w0.x + xh1 * w1.x + xh2 * w2.x;
                    float sh1 = bb.y + xh0 * w0.y + xh1 * w1.y + xh2 * w2.y;
                    A[m][kc][h8 * 2]     = pack_h2(sl0, sl1);
                    A[m][kc][h8 * 2 + 1] = pack_h2(sh0, sh1);
                }
            }
            #pragma unroll
            for (int kc = 2; kc < 4; kc++) {          // noise cols 32..63
                #pragma unroll
                for (int h8 = 0; h8 < 2; h8++) {
                    int nc = (kc - 2) * 16 + 2 * c + h8 * 8;
                    float2 nl = vl ? *(const float2*)(noise + rl * 32 + nc) : make_float2(0, 0);
                    float2 nh = vh ? *(const float2*)(noise + rh * 32 + nc) : make_float2(0, 0);
                    A[m][kc][h8 * 2]     = pack_h2(nl.x, nl.y);
                    A[m][kc][h8 * 2 + 1] = pack_h2(nh.x, nh.y);
                }
            }
        }

        // ---- L2 prefetch for the NEXT tile this CTA will process ----
        {
            long nt = (long)t + gridDim.x;
            if (nt < nTiles) {
                long nb0 = nt * TILE_M + lrow0;
                #pragma unroll
                for (int m = 0; m < 2; m++) {
                    long rl = nb0 + m * 16;
                    if (rl < N) {
                        prefetch_l2(noise + rl * 32);        // 128B noise row (lo)
                        prefetch_l2(noise + (rl + 8) * 32);  // 128B noise row (hi)
                        prefetch_l2(x + rl * 3);             // x rows
                        prefetch_l2(x + (rl + 8) * 3);
                    }
                }
            }
        }

        // ---- 7 layers (fully unrolled): LDS.128 frags serve 2 nb x 2 m MMAs ----
        float acc[2][8][4];
        #pragma unroll
        for (int l = 0; l < 7; l++) {
            #pragma unroll
            for (int nb = 0; nb < 8; nb++) {
                float2 bb = *(const float2*)(biasS + l * 64 + nb * 8 + 2 * c);
                #pragma unroll
                for (int m = 0; m < 2; m++) {
                    acc[m][nb][0] = bb.x; acc[m][nb][1] = bb.y;
                    acc[m][nb][2] = bb.x; acc[m][nb][3] = bb.y;
                }
            }
            #pragma unroll
            for (int kc = 0; kc < 4; kc++) {
                const uint4* pw = Wfr4 + ((l * 4 + kc) * 4) * 32 + lane;
                uint4 q[4];
                #pragma unroll
                for (int p = 0; p < 4; p++) q[p] = pw[p * 32];
                #pragma unroll
                for (int p = 0; p < 4; p++) {
                    int nb0 = 2 * p, nb1 = 2 * p + 1;
                    mma_f16(acc[0][nb0][0], acc[0][nb0][1], acc[0][nb0][2], acc[0][nb0][3],
                            A[0][kc][0], A[0][kc][1], A[0][kc][2], A[0][kc][3],
                            q[p].x, q[p].y);
                    mma_f16(acc[1][nb0][0], acc[1][nb0][1], acc[1][nb0][2], acc[1][nb0][3],
                            A[1][kc][0], A[1][kc][1], A[1][kc][2], A[1][kc][3],
                            q[p].x, q[p].y);
                    mma_f16(acc[0][nb1][0], acc[0][nb1][1], acc[0][nb1][2], acc[0][nb1][3],
                            A[0][kc][0], A[0][kc][1], A[0][kc][2], A[0][kc][3],
                            q[p].z, q[p].w);
                    mma_f16(acc[1][nb1][0], acc[1][nb1][1], acc[1][nb1][2], acc[1][nb1][3],
                            A[1][kc][0], A[1][kc][1], A[1][kc][2], A[1][kc][3],
                            q[p].z, q[p].w);
                }
            }
            if (l < 6) {
                // C-frag (nb pair 2kc, 2kc+1) -> next-layer A-frag kc, ReLU in h2
                #pragma unroll
                for (int m = 0; m < 2; m++)
                    #pragma unroll
                    for (int kc = 0; kc < 4; kc++) {
                        A[m][kc][0] = pack_relu_h2(acc[m][2 * kc][0], acc[m][2 * kc][1]);
                        A[m][kc][1] = pack_relu_h2(acc[m][2 * kc][2], acc[m][2 * kc][3]);
                        A[m][kc][2] = pack_relu_h2(acc[m][2 * kc + 1][0], acc[m][2 * kc + 1][1]);
                        A[m][kc][3] = pack_relu_h2(acc[m][2 * kc + 1][2], acc[m][2 * kc + 1][3]);
                    }
            }
        }

        // ---- head epilogue: stage rgb (cols 0..31) + sigma (col 32) per-warp ----
        #pragma unroll
        for (int m = 0; m < 2; m++) {
            int sl = lrow0 + m * 16;     // tile-local rows
            int sh = sl + 8;
            #pragma unroll
            for (int nb = 0; nb < 4; nb++) {
                int j = nb * 8 + 2 * c;
                smOut[sl * 33 + j]     = acc[m][nb][0];
                smOut[sl * 33 + j + 1] = acc[m][nb][1];
                smOut[sh * 33 + j]     = acc[m][nb][2];
                smOut[sh * 33 + j + 1] = acc[m][nb][3];
            }
            if (c == 0) {
                smOut[sl * 33 + 32] = acc[m][4][0];
                smOut[sh * 33 + 32] = acc[m][4][2];
            }
        }
        __syncwarp();
        {
            long gBase = (long)t * (TILE_M * 33) + (long)wid * (32 * 33);
            int  sBase = wid * (32 * 33);
            long rowsLeft = N - (long)t * TILE_M - wid * 32;
            if (rowsLeft >= 32) {
                // full warp-chunk: 1056 floats = 264 float4 (all bases 16B-aligned)
                const float4* s4 = (const float4*)(smOut + sBase);
                float4*       g4 = (float4*)(out + gBase);
                #pragma unroll
                for (int it = 0; it < 8; it++)
                    g4[lane + it * 32] = s4[lane + it * 32];
                if (lane < 8) g4[lane + 256] = s4[lane + 256];
            } else if (rowsLeft > 0) {
                int nfl = (int)rowsLeft * 33;
                for (int i = lane; i < nfl; i += 32)
                    out[gBase + i] = smOut[sBase + i];
            }
        }
        __syncwarp();
    }
}

extern "C" void kernel_launch(void* const* d_in, const int* in_sizes, int n_in,
                              void* d_out, int out_size) {
    const float* x       = (const float*)d_in[0];
    const float* noise   = (const float*)d_in[1];
    const float* stem_w  = (const float*)d_in[2];
    const float* stem_b  = (const float*)d_in[3];
    const float* Ws      = (const float*)d_in[4];
    const float* bs      = (const float*)d_in[5];
    const float* sigma_w = (const float*)d_in[6];
    const float* sigma_b = (const float*)d_in[7];
    const float* rgb_w   = (const float*)d_in[8];
    const float* rgb_b   = (const float*)d_in[9];
    float* out = (float*)d_out;

    int N = in_sizes[0] / 3;
    int nTiles = (N + TILE_M - 1) / TILE_M;   // ceil(2,097,152 / 384) = 5462

    cudaFuncSetAttribute(nerf_mlp_kernel,
                         cudaFuncAttributeMaxDynamicSharedMemorySize, SMEM_BYTES);

    int dev = 0, sms = 148;
    cudaGetDevice(&dev);
    cudaDeviceGetAttribute(&sms, cudaDevAttrMultiProcessorCount, dev);
    int grid = nTiles < sms ? nTiles : sms;

    nerf_mlp_kernel<<<grid, 384, SMEM_BYTES>>>(
        x, noise, stem_w, stem_b, Ws, bs, sigma_w, sigma_b, rgb_w, rgb_b,
        out, N, nTiles);
}